// round 1
// baseline (speedup 1.0000x reference)
#include <cuda_runtime.h>

// Problem shape (fixed by the dataset)
#define R_ROWS 8192
#define N_FEAT 4096
#define NP1    4097

// Extracted structure of w_lb / w_ub: w = [[diag(d), bias],[0,1]]
__device__ float g_diag_lb[N_FEAT];
__device__ float g_diag_ub[N_FEAT];
__device__ float g_bias_lb[N_FEAT];
__device__ float g_bias_ub[N_FEAT];

__global__ void extract_struct_kernel(const float* __restrict__ wlb,
                                      const float* __restrict__ wub) {
    int j = blockIdx.x * blockDim.x + threadIdx.x;
    if (j < N_FEAT) {
        size_t row = (size_t)j * NP1;
        g_diag_lb[j] = wlb[row + j];
        g_bias_lb[j] = wlb[row + N_FEAT];
        g_diag_ub[j] = wub[row + j];
        g_bias_ub[j] = wub[row + N_FEAT];
    }
}

// grid = 2*R_ROWS blocks: block b < R handles new_lb row b, block b >= R handles
// new_ub row (b - R). Output is the concatenation [new_lb ; new_ub], so the
// output row offset is just b * NP1.
__global__ __launch_bounds__(256, 8)
void relu_backsub_kernel(const float* __restrict__ lb,
                         const float* __restrict__ ub,
                         float* __restrict__ out) {
    const int b = blockIdx.x;
    const bool is_ub = (b >= R_ROWS);
    const int r = is_ub ? (b - R_ROWS) : b;

    const float* __restrict__ x = (is_ub ? ub : lb) + (size_t)r * NP1;
    float* __restrict__ o = out + (size_t)b * NP1;

    // Role swap for the ub rows: (dl,du,bl,bu) -> (du,dl,bu,bl)
    const float* __restrict__ dA = is_ub ? g_diag_ub : g_diag_lb;
    const float* __restrict__ dB = is_ub ? g_diag_lb : g_diag_ub;
    const float* __restrict__ bA = is_ub ? g_bias_ub : g_bias_lb;
    const float* __restrict__ bB = is_ub ? g_bias_lb : g_bias_ub;

    float acc = 0.0f;
    const int t = threadIdx.x;

    // N_FEAT / 256 = 16 iterations, fixed trip count -> fully unrolled,
    // loads front-batched for MLP. Perfectly coalesced 32-bit accesses.
#pragma unroll
    for (int it = 0; it < N_FEAT / 256; ++it) {
        const int j = t + it * 256;
        const float v = x[j];
        const float p = fmaxf(v, 0.0f);
        const float n = fmaxf(-v, 0.0f);
        o[j] = p * dA[j] - n * dB[j];
        acc = fmaf(p, bA[j], acc);
        acc = fmaf(-n, bB[j], acc);
    }

    // Block reduction of the bias-column dot product.
    __shared__ float red[8];
#pragma unroll
    for (int off = 16; off > 0; off >>= 1)
        acc += __shfl_down_sync(0xffffffffu, acc, off);
    const int lane = t & 31;
    const int wid = t >> 5;
    if (lane == 0) red[wid] = acc;
    __syncthreads();
    if (t == 0) {
        float tot = 0.0f;
#pragma unroll
        for (int i = 0; i < 8; ++i) tot += red[i];
        // relu(x)-relu(-x) = x for the passthrough last element.
        o[N_FEAT] = tot + x[N_FEAT];
    }
}

extern "C" void kernel_launch(void* const* d_in, const int* in_sizes, int n_in,
                              void* d_out, int out_size) {
    const float* lb  = (const float*)d_in[0];
    const float* ub  = (const float*)d_in[1];
    const float* wlb = (const float*)d_in[2];
    const float* wub = (const float*)d_in[3];
    float* out = (float*)d_out;

    extract_struct_kernel<<<(N_FEAT + 255) / 256, 256>>>(wlb, wub);
    relu_backsub_kernel<<<2 * R_ROWS, 256>>>(lb, ub, out);
}